// round 8
// baseline (speedup 1.0000x reference)
#include <cuda_runtime.h>
#include <cuda_bf16.h>
#include <cstdint>

// Problem constants
constexpr int M = 16384;   // batch
constexpr int N = 1024;    // out features
constexpr int K = 1024;    // in features

// GEMM tiling
constexpr int BM = 128, BN = 128, BK = 32;
constexpr int ROWB = 80;     // bytes per SMEM row (64B data + 16B pad: conflict-free ldmatrix)

// SMEM stage layout (double buffered)
constexpr int T_AH = 0;
constexpr int T_AL = BM * ROWB;          // 10240
constexpr int T_BH = 2 * BM * ROWB;      // 20480
constexpr int T_BL = 3 * BM * ROWB;      // 30720
constexpr int STG  = 4 * BM * ROWB;      // 40960 per stage
constexpr int SMEM_TOTAL = 2 * STG;      // 81920

// Precomputed bf16 hi/lo splits (static device globals; no allocs)
__device__ __nv_bfloat16 g_Ah[M * K];    // 32 MB
__device__ __nv_bfloat16 g_Al[M * K];    // 32 MB
__device__ __nv_bfloat16 g_Bh[N * K];    // 2 MB
__device__ __nv_bfloat16 g_Bl[N * K];    // 2 MB

// ---------------------------------------------------------------------------
// Kernel 0: split x -> bf16 hi/lo  (HBM-bound elementwise pass)
// ---------------------------------------------------------------------------
__global__ void split_x(const float* __restrict__ x) {
    size_t i = (size_t)blockIdx.x * blockDim.x + threadIdx.x;   // over M*K/4 float4s
    float4 f = ((const float4*)x)[i];
    __nv_bfloat162 h0 = __float22bfloat162_rn(make_float2(f.x, f.y));
    __nv_bfloat162 h1 = __float22bfloat162_rn(make_float2(f.z, f.w));
    __nv_bfloat162 l0 = __float22bfloat162_rn(make_float2(
        f.x - __bfloat162float(h0.x), f.y - __bfloat162float(h0.y)));
    __nv_bfloat162 l1 = __float22bfloat162_rn(make_float2(
        f.z - __bfloat162float(h1.x), f.w - __bfloat162float(h1.y)));
    uint2 uh = make_uint2(*(uint32_t*)&h0, *(uint32_t*)&h1);
    uint2 ul = make_uint2(*(uint32_t*)&l0, *(uint32_t*)&l1);
    ((uint2*)g_Ah)[i] = uh;
    ((uint2*)g_Al)[i] = ul;
}

// ---------------------------------------------------------------------------
// Kernel 1: weight normalization -> bf16 hi/lo splits + jacobian-log output
// ---------------------------------------------------------------------------
__global__ void prep_kernel(const float* __restrict__ W,
                            const float* __restrict__ ls,
                            const int* __restrict__ dmask,
                            const int* __restrict__ tmask,
                            float* __restrict__ jac) {
    int r = blockIdx.x;
    int t = threadIdx.x;
    const int rowoff = r * K;

    float wm[4];
    float ss = 0.f;
#pragma unroll
    for (int i = 0; i < 4; i++) {
        int c = t + i * 256;
        float w = W[rowoff + c];
        float v = dmask[rowoff + c] ? expf(w) : (tmask[rowoff + c] ? w : 0.f);
        wm[i] = v;
        ss += v * v;
    }

    __shared__ float warpsum[8];
    __shared__ float s_norm;
#pragma unroll
    for (int o = 16; o > 0; o >>= 1) ss += __shfl_xor_sync(0xffffffffu, ss, o);
    if ((t & 31) == 0) warpsum[t >> 5] = ss;
    __syncthreads();
    if (t == 0) {
        float s = 0.f;
#pragma unroll
        for (int i = 0; i < 8; i++) s += warpsum[i];
        s_norm = sqrtf(s);
    }
    __syncthreads();

    float norm  = s_norm;
    float lsr   = ls[r];
    float scale = expf(lsr) / norm;
    int blk = r >> 3;
    int c_lo = blk * 8, c_hi = c_lo + 8;

#pragma unroll
    for (int i = 0; i < 4; i++) {
        int c = t + i * 256;
        float v = wm[i] * scale;
        __nv_bfloat16 hi = __float2bfloat16_rn(v);
        __nv_bfloat16 lo = __float2bfloat16_rn(v - __bfloat162float(hi));
        g_Bh[rowoff + c] = hi;
        g_Bl[rowoff + c] = lo;
        if (c >= c_lo && c < c_hi) {
            jac[blk * 64 + (r & 7) * 8 + (c - c_lo)] = W[rowoff + c] + lsr - logf(norm);
        }
    }
}

// ---------------------------------------------------------------------------
// PTX helpers
// ---------------------------------------------------------------------------
__device__ __forceinline__ uint32_t smem_u32(const void* p) {
    uint32_t a;
    asm("{ .reg .u64 t; cvta.to.shared.u64 t, %1; cvt.u32.u64 %0, t; }" : "=r"(a) : "l"(p));
    return a;
}

__device__ __forceinline__ void cp16(uint32_t dst, const void* src) {
    asm volatile("cp.async.cg.shared.global [%0], [%1], 16;" :: "r"(dst), "l"(src) : "memory");
}

__device__ __forceinline__ void ldsm_x4(uint32_t& r0, uint32_t& r1, uint32_t& r2, uint32_t& r3,
                                        uint32_t addr) {
    asm volatile("ldmatrix.sync.aligned.m8n8.x4.shared.b16 {%0,%1,%2,%3}, [%4];"
                 : "=r"(r0), "=r"(r1), "=r"(r2), "=r"(r3) : "r"(addr));
}

__device__ __forceinline__ void mma_16816(float* d, const uint32_t* a, const uint32_t* b) {
    asm volatile(
        "mma.sync.aligned.m16n8k16.row.col.f32.bf16.bf16.f32 "
        "{%0,%1,%2,%3}, {%4,%5,%6,%7}, {%8,%9}, {%0,%1,%2,%3};"
        : "+f"(d[0]), "+f"(d[1]), "+f"(d[2]), "+f"(d[3])
        : "r"(a[0]), "r"(a[1]), "r"(a[2]), "r"(a[3]), "r"(b[0]), "r"(b[1]));
}

// ---------------------------------------------------------------------------
// Kernel 2: cp.async-only split-bf16 HMMA GEMM  y = x @ Wn^T + bias
// All operands pre-split in GMEM; mainloop = cp.async fill + ldmatrix + mma.
// CTA 128x128, BK=32, double-buffered; Kmax = n0 + 128.
// ---------------------------------------------------------------------------
__global__ __launch_bounds__(256, 2)
void gemm_mma(const float* __restrict__ bias,
              float* __restrict__ C) {
    extern __shared__ __align__(16) char smem[];
    const uint32_t sb = smem_u32(smem);

    const int tid  = threadIdx.x;
    const int wid  = tid >> 5;
    const int lane = tid & 31;

    // heavy n-tiles first
    const int ntile = 7 - (int)blockIdx.x;
    const int n0 = ntile * BN;
    const int m0 = (int)blockIdx.y * BM;
    const int Kmax = n0 + BN;
    const int nch  = Kmax / BK;

    const int wm = wid & 1;            // 0..1  (M)
    const int wn = wid >> 1;           // 0..3  (N)

    float acc[4][4][4];
#pragma unroll
    for (int i = 0; i < 4; i++)
#pragma unroll
        for (int j = 0; j < 4; j++)
#pragma unroll
            for (int r = 0; r < 4; r++) acc[i][j][r] = 0.f;

    // fill coordinates: thread -> (row base, 16B segment)
    const int seg = tid & 3;           // 16B segment within 64B row
    const int r0  = tid >> 2;          // 0..63

    auto issue = [&](int c, int st) {
        int k0 = c * BK;
        uint32_t base = sb + st * STG;
#pragma unroll
        for (int i = 0; i < 2; i++) {
            int row = r0 + i * 64;
            uint32_t d = base + (uint32_t)(row * ROWB + seg * 16);
            size_t aoff = (size_t)(m0 + row) * K + k0 + seg * 8;
            size_t boff = (size_t)(n0 + row) * K + k0 + seg * 8;
            cp16(d + T_AH, g_Ah + aoff);
            cp16(d + T_AL, g_Al + aoff);
            cp16(d + T_BH, g_Bh + boff);
            cp16(d + T_BL, g_Bl + boff);
        }
        asm volatile("cp.async.commit_group;" ::: "memory");
    };

    auto mmaStage = [&](int st) {
        const uint32_t ah_b = sb + st * STG + T_AH;
        const uint32_t al_b = sb + st * STG + T_AL;
        const uint32_t bh_b = sb + st * STG + T_BH;
        const uint32_t bl_b = sb + st * STG + T_BL;
#pragma unroll
        for (int ks = 0; ks < 2; ks++) {
            const uint32_t kbyte = ks * 32;

            uint32_t bh[4][2], bl[4][2];
            {
                int nrow = (lane & 7) + ((lane & 16) ? 8 : 0);
                uint32_t kseg = ((lane >> 3) & 1) * 16;
#pragma unroll
                for (int half = 0; half < 2; half++) {
                    uint32_t addr_off = (uint32_t)((wn * 32 + half * 16 + nrow) * ROWB) + kbyte + kseg;
                    ldsm_x4(bh[half*2][0], bh[half*2][1], bh[half*2+1][0], bh[half*2+1][1],
                            bh_b + addr_off);
                    ldsm_x4(bl[half*2][0], bl[half*2][1], bl[half*2+1][0], bl[half*2+1][1],
                            bl_b + addr_off);
                }
            }

            int mrow = lane & 15;
            uint32_t akseg = (uint32_t)(lane >> 4) * 16;
#pragma unroll
            for (int mi = 0; mi < 4; mi++) {
                uint32_t aoff = (uint32_t)((wm * 64 + mi * 16 + mrow) * ROWB) + kbyte + akseg;
                uint32_t ah[4], al[4];
                ldsm_x4(ah[0], ah[1], ah[2], ah[3], ah_b + aoff);
                ldsm_x4(al[0], al[1], al[2], al[3], al_b + aoff);
#pragma unroll
                for (int nj = 0; nj < 4; nj++) mma_16816(acc[mi][nj], ah, bh[nj]);
#pragma unroll
                for (int nj = 0; nj < 4; nj++) mma_16816(acc[mi][nj], ah, bl[nj]);
#pragma unroll
                for (int nj = 0; nj < 4; nj++) mma_16816(acc[mi][nj], al, bh[nj]);
            }
        }
    };

    // prologue
    issue(0, 0);

    for (int c = 0; c < nch; ++c) {
        int s = c & 1;
        bool more = (c + 1 < nch);
        if (more) {
            issue(c + 1, s ^ 1);
            asm volatile("cp.async.wait_group 1;" ::: "memory");
        } else {
            asm volatile("cp.async.wait_group 0;" ::: "memory");
        }
        __syncthreads();           // stage s complete & visible to all warps
        mmaStage(s);
        __syncthreads();           // all reads of stage s done before next overwrite
    }

    // ---- epilogue: add bias, store ----
    const int crow = lane >> 2;
    const int ccol = (lane & 3) * 2;
#pragma unroll
    for (int nj = 0; nj < 4; nj++) {
        int col = n0 + wn * 32 + nj * 8 + ccol;
        float2 bv = *(const float2*)(bias + col);
#pragma unroll
        for (int mi = 0; mi < 4; mi++) {
            int row = m0 + wm * 64 + mi * 16 + crow;
            float2 o0, o1;
            o0.x = acc[mi][nj][0] + bv.x;
            o0.y = acc[mi][nj][1] + bv.y;
            o1.x = acc[mi][nj][2] + bv.x;
            o1.y = acc[mi][nj][3] + bv.y;
            *(float2*)(C + (size_t)row * N + col)       = o0;
            *(float2*)(C + (size_t)(row + 8) * N + col) = o1;
        }
    }
}

// ---------------------------------------------------------------------------
// Launch
// ---------------------------------------------------------------------------
extern "C" void kernel_launch(void* const* d_in, const int* in_sizes, int n_in,
                              void* d_out, int out_size) {
    const float* x     = (const float*)d_in[0];
    const float* W     = (const float*)d_in[1];
    const float* bias  = (const float*)d_in[2];
    const float* ls    = (const float*)d_in[3];
    const int*   dmask = (const int*)d_in[4];
    const int*   tmask = (const int*)d_in[5];

    float* y   = (float*)d_out;
    float* jac = y + (size_t)M * N;

    cudaFuncSetAttribute(gemm_mma, cudaFuncAttributeMaxDynamicSharedMemorySize, SMEM_TOTAL);

    split_x<<<(M * K / 4) / 512, 512>>>(x);
    prep_kernel<<<N, 256>>>(W, ls, dmask, tmask, jac);
    gemm_mma<<<dim3(N / BN, M / BM), 256, SMEM_TOTAL>>>(bias, y);
}

// round 10
// speedup vs baseline: 1.4585x; 1.4585x over previous
#include <cuda_runtime.h>
#include <cuda_fp16.h>
#include <cstdint>

// Problem constants
constexpr int M = 16384;   // batch
constexpr int N = 1024;    // out features
constexpr int K = 1024;    // in features

// GEMM tiling
constexpr int BM = 128, BN = 128, BK = 32;
constexpr int ROWB = 80;     // bytes per SMEM row (64B data + 16B pad: conflict-free ldmatrix)

// SMEM stage layout (3 tiles per stage, 3 stages)
constexpr int T_A  = 0;
constexpr int T_BH = BM * ROWB;          // 10240
constexpr int T_BL = 2 * BM * ROWB;      // 20480
constexpr int STG  = 3 * BM * ROWB;      // 30720 per stage
constexpr int NSTAGE = 3;
constexpr int SMEM_TOTAL = NSTAGE * STG; // 92160

// Precomputed operands (static device globals; no allocs)
__device__ __half g_A16[M * K];          // 32 MB  fp16(x)
__device__ __half g_Bh[N * K];           // 2 MB   fp16 hi of Wn
__device__ __half g_Bl[N * K];           // 2 MB   fp16 lo of Wn

// ---------------------------------------------------------------------------
// Kernel 0: convert x -> fp16  (HBM-bound elementwise pass)
// ---------------------------------------------------------------------------
__global__ void conv_x(const float* __restrict__ x) {
    size_t i = (size_t)blockIdx.x * blockDim.x + threadIdx.x;   // over M*K/4 float4s
    float4 f = ((const float4*)x)[i];
    __half2 h0 = __float22half2_rn(make_float2(f.x, f.y));
    __half2 h1 = __float22half2_rn(make_float2(f.z, f.w));
    uint2 u = make_uint2(*(uint32_t*)&h0, *(uint32_t*)&h1);
    ((uint2*)g_A16)[i] = u;
}

// ---------------------------------------------------------------------------
// Kernel 1: weight normalization -> fp16 hi/lo splits + jacobian-log output
// ---------------------------------------------------------------------------
__global__ void prep_kernel(const float* __restrict__ W,
                            const float* __restrict__ ls,
                            const int* __restrict__ dmask,
                            const int* __restrict__ tmask,
                            float* __restrict__ jac) {
    int r = blockIdx.x;
    int t = threadIdx.x;
    const int rowoff = r * K;

    float wm[4];
    float ss = 0.f;
#pragma unroll
    for (int i = 0; i < 4; i++) {
        int c = t + i * 256;
        float w = W[rowoff + c];
        float v = dmask[rowoff + c] ? expf(w) : (tmask[rowoff + c] ? w : 0.f);
        wm[i] = v;
        ss += v * v;
    }

    __shared__ float warpsum[8];
    __shared__ float s_norm;
#pragma unroll
    for (int o = 16; o > 0; o >>= 1) ss += __shfl_xor_sync(0xffffffffu, ss, o);
    if ((t & 31) == 0) warpsum[t >> 5] = ss;
    __syncthreads();
    if (t == 0) {
        float s = 0.f;
#pragma unroll
        for (int i = 0; i < 8; i++) s += warpsum[i];
        s_norm = sqrtf(s);
    }
    __syncthreads();

    float norm  = s_norm;
    float lsr   = ls[r];
    float scale = expf(lsr) / norm;
    int blk = r >> 3;
    int c_lo = blk * 8, c_hi = c_lo + 8;

#pragma unroll
    for (int i = 0; i < 4; i++) {
        int c = t + i * 256;
        float v = wm[i] * scale;
        __half hi = __float2half_rn(v);
        __half lo = __float2half_rn(v - __half2float(hi));
        g_Bh[rowoff + c] = hi;
        g_Bl[rowoff + c] = lo;
        if (c >= c_lo && c < c_hi) {
            jac[blk * 64 + (r & 7) * 8 + (c - c_lo)] = W[rowoff + c] + lsr - logf(norm);
        }
    }
}

// ---------------------------------------------------------------------------
// PTX helpers
// ---------------------------------------------------------------------------
__device__ __forceinline__ uint32_t smem_u32(const void* p) {
    uint32_t a;
    asm("{ .reg .u64 t; cvta.to.shared.u64 t, %1; cvt.u32.u64 %0, t; }" : "=r"(a) : "l"(p));
    return a;
}

__device__ __forceinline__ void cp16(uint32_t dst, const void* src) {
    asm volatile("cp.async.cg.shared.global [%0], [%1], 16;" :: "r"(dst), "l"(src) : "memory");
}

__device__ __forceinline__ void ldsm_x4(uint32_t& r0, uint32_t& r1, uint32_t& r2, uint32_t& r3,
                                        uint32_t addr) {
    asm volatile("ldmatrix.sync.aligned.m8n8.x4.shared.b16 {%0,%1,%2,%3}, [%4];"
                 : "=r"(r0), "=r"(r1), "=r"(r2), "=r"(r3) : "r"(addr));
}

__device__ __forceinline__ void mma_16816(float* d, const uint32_t* a, const uint32_t* b) {
    asm volatile(
        "mma.sync.aligned.m16n8k16.row.col.f32.f16.f16.f32 "
        "{%0,%1,%2,%3}, {%4,%5,%6,%7}, {%8,%9}, {%0,%1,%2,%3};"
        : "+f"(d[0]), "+f"(d[1]), "+f"(d[2]), "+f"(d[3])
        : "r"(a[0]), "r"(a[1]), "r"(a[2]), "r"(a[3]), "r"(b[0]), "r"(b[1]));
}

// ---------------------------------------------------------------------------
// Kernel 2: 2-product fp16 HMMA GEMM  y = x @ Wn^T + bias
//   D = A16·Bh + A16·Bl   (B split hi/lo; error ~ fp16 quantization of A)
// CTA 128x128, BK=32, 3-stage cp.async pipeline, one barrier per chunk.
// Block-triangular: Kmax = n0 + 128.
// ---------------------------------------------------------------------------
__global__ __launch_bounds__(256, 2)
void gemm_mma(const float* __restrict__ bias,
              float* __restrict__ C) {
    extern __shared__ __align__(16) char smem[];
    const uint32_t sb = smem_u32(smem);

    const int tid  = threadIdx.x;
    const int wid  = tid >> 5;
    const int lane = tid & 31;

    // heavy n-tiles first
    const int ntile = 7 - (int)blockIdx.x;
    const int n0 = ntile * BN;
    const int m0 = (int)blockIdx.y * BM;
    const int Kmax = n0 + BN;
    const int nch  = Kmax / BK;

    const int wm = wid & 1;            // 0..1  (M)
    const int wn = wid >> 1;           // 0..3  (N)

    float acc[4][4][4];
#pragma unroll
    for (int i = 0; i < 4; i++)
#pragma unroll
        for (int j = 0; j < 4; j++)
#pragma unroll
            for (int r = 0; r < 4; r++) acc[i][j][r] = 0.f;

    // fill coordinates: thread -> (row base, 16B segment)
    const int seg = tid & 3;           // 16B segment within 64B row
    const int r0  = tid >> 2;          // 0..63

    auto issue = [&](int c, int st) {
        int k0 = c * BK;
        uint32_t base = sb + st * STG;
#pragma unroll
        for (int i = 0; i < 2; i++) {
            int row = r0 + i * 64;
            uint32_t d = base + (uint32_t)(row * ROWB + seg * 16);
            size_t aoff = (size_t)(m0 + row) * K + k0 + seg * 8;
            size_t boff = (size_t)(n0 + row) * K + k0 + seg * 8;
            cp16(d + T_A,  g_A16 + aoff);
            cp16(d + T_BH, g_Bh + boff);
            cp16(d + T_BL, g_Bl + boff);
        }
        asm volatile("cp.async.commit_group;" ::: "memory");
    };

    auto mmaStage = [&](int st) {
        const uint32_t a_b  = sb + st * STG + T_A;
        const uint32_t bh_b = sb + st * STG + T_BH;
        const uint32_t bl_b = sb + st * STG + T_BL;
#pragma unroll
        for (int ks = 0; ks < 2; ks++) {
            const uint32_t kbyte = ks * 32;

            uint32_t bh[4][2], bl[4][2];
            {
                int nrow = (lane & 7) + ((lane & 16) ? 8 : 0);
                uint32_t kseg = ((lane >> 3) & 1) * 16;
#pragma unroll
                for (int half = 0; half < 2; half++) {
                    uint32_t addr_off = (uint32_t)((wn * 32 + half * 16 + nrow) * ROWB) + kbyte + kseg;
                    ldsm_x4(bh[half*2][0], bh[half*2][1], bh[half*2+1][0], bh[half*2+1][1],
                            bh_b + addr_off);
                    ldsm_x4(bl[half*2][0], bl[half*2][1], bl[half*2+1][0], bl[half*2+1][1],
                            bl_b + addr_off);
                }
            }

            int mrow = lane & 15;
            uint32_t akseg = (uint32_t)(lane >> 4) * 16;
#pragma unroll
            for (int mi = 0; mi < 4; mi++) {
                uint32_t aoff = (uint32_t)((wm * 64 + mi * 16 + mrow) * ROWB) + kbyte + akseg;
                uint32_t a[4];
                ldsm_x4(a[0], a[1], a[2], a[3], a_b + aoff);
#pragma unroll
                for (int nj = 0; nj < 4; nj++) mma_16816(acc[mi][nj], a, bh[nj]);
#pragma unroll
                for (int nj = 0; nj < 4; nj++) mma_16816(acc[mi][nj], a, bl[nj]);
            }
        }
    };

    // prologue: fill first two stages
    issue(0, 0);
    if (nch > 1) issue(1, 1);

    for (int c = 0; c < nch; ++c) {
        if (c + 1 < nch) {
            asm volatile("cp.async.wait_group 1;" ::: "memory");   // group c done
        } else {
            asm volatile("cp.async.wait_group 0;" ::: "memory");
        }
        __syncthreads();                 // stage c%3 visible; prior readers of (c+2)%3 done
        mmaStage(c % NSTAGE);
        if (c + 2 < nch) issue(c + 2, (c + 2) % NSTAGE);
    }

    // ---- epilogue: add bias, store ----
    const int crow = lane >> 2;
    const int ccol = (lane & 3) * 2;
#pragma unroll
    for (int nj = 0; nj < 4; nj++) {
        int col = n0 + wn * 32 + nj * 8 + ccol;
        float2 bv = *(const float2*)(bias + col);
#pragma unroll
        for (int mi = 0; mi < 4; mi++) {
            int row = m0 + wm * 64 + mi * 16 + crow;
            float2 o0, o1;
            o0.x = acc[mi][nj][0] + bv.x;
            o0.y = acc[mi][nj][1] + bv.y;
            o1.x = acc[mi][nj][2] + bv.x;
            o1.y = acc[mi][nj][3] + bv.y;
            *(float2*)(C + (size_t)row * N + col)       = o0;
            *(float2*)(C + (size_t)(row + 8) * N + col) = o1;
        }
    }
}

// ---------------------------------------------------------------------------
// Launch
// ---------------------------------------------------------------------------
extern "C" void kernel_launch(void* const* d_in, const int* in_sizes, int n_in,
                              void* d_out, int out_size) {
    const float* x     = (const float*)d_in[0];
    const float* W     = (const float*)d_in[1];
    const float* bias  = (const float*)d_in[2];
    const float* ls    = (const float*)d_in[3];
    const int*   dmask = (const int*)d_in[4];
    const int*   tmask = (const int*)d_in[5];

    float* y   = (float*)d_out;
    float* jac = y + (size_t)M * N;

    cudaFuncSetAttribute(gemm_mma, cudaFuncAttributeMaxDynamicSharedMemorySize, SMEM_TOTAL);

    conv_x<<<(M * K / 4) / 512, 512>>>(x);
    prep_kernel<<<N, 256>>>(W, ls, dmask, tmask, jac);
    gemm_mma<<<dim3(N / BN, M / BM), 256, SMEM_TOTAL>>>(bias, y);
}